// round 15
// baseline (speedup 1.0000x reference)
#include <cuda_runtime.h>
#include <math.h>

#define TT 32
#define DD 256
#define HH 768
#define GRIDN 128
#define NT 256

#define OFF_HXLAST (TT*128*HH)
#define OFF_PC     (OFF_HXLAST + 128*HH)
#define OFF_STEPS  (OFF_PC + 128)

// persistent scratch (allocation-free rule)
__device__ float g_hxi[2][128][HH];               // double-buffered hidden state
__device__ float g_pd[8*128*32];                  // partial ponder dots [n][row][cg]
__device__ __align__(16) unsigned g_flags[GRIDN]; // barrier flags (monotonic)

struct SM {
  float whh[24][HH];     // W_hh rows for this block's 24 cols (73728 B)
  float wih[24][260];    // W_ih rows, k<256 (+pad)           (24960 B)
  float base[32][26];    // x@Wih^T + bias per step
  float hxn[32][26];     // hx_new tile
  float ahx[32][26];     // accum_hx tile
  float flagw[24];
  float wp[24];
  float bias[24];
  float ah[32], sc[32], spc[32], coef[32], pc[32];
  int   mask[32];
};

// group-scoped flag barrier: 32 blocks of this row group only
__device__ __forceinline__ void gbar(unsigned ep, int rg){
  __syncthreads();
  if (threadIdx.x == 0)
    asm volatile("st.release.gpu.global.u32 [%0], %1;"
                 :: "l"(&g_flags[blockIdx.x]), "r"(ep) : "memory");
  if (threadIdx.x < 8){
    const unsigned* fp = g_flags + rg*32 + threadIdx.x*4;
    for(;;){
      unsigned a,b,c,d;
      asm volatile("ld.relaxed.gpu.global.v4.u32 {%0,%1,%2,%3}, [%4];"
                   : "=r"(a),"=r"(b),"=r"(c),"=r"(d) : "l"(fp) : "memory");
      if ((int)(a-ep)>=0 && (int)(b-ep)>=0 && (int)(c-ep)>=0 && (int)(d-ep)>=0) break;
      __nanosleep(64);
    }
    asm volatile("fence.acq_rel.gpu;" ::: "memory");
  }
  __syncthreads();
}

// GEMM: warp = 4 rows x 24 cols; lane = cgp*8 + kl (cgp: col sextet, kl: K/8 split).
// Per thread: acc[4][6], 2304 FFMA (@NIT=24), 144 LDS.128, depth-3 x prefetch.
// Wc must point at column cgp*6 of the weight tile.
template<int NIT, int WS, bool CG>
__device__ __forceinline__ void gemm6(float (&acc)[4][6],
    const float* xrow0, int xstride, const float* Wc, int kl)
{
  const float4* xq[4];
  #pragma unroll
  for (int r = 0; r < 4; r++) xq[r] = (const float4*)(xrow0 + r*xstride);

  float4 q0[4], q1[4], q2[4], qn[4];
  #pragma unroll
  for (int r = 0; r < 4; r++){
    q0[r] = CG ? __ldcg(xq[r] + kl)      : __ldg(xq[r] + kl);
    q1[r] = CG ? __ldcg(xq[r] + 8 + kl)  : __ldg(xq[r] + 8 + kl);
    q2[r] = CG ? __ldcg(xq[r] + 16 + kl) : __ldg(xq[r] + 16 + kl);
  }

  #pragma unroll
  for (int it = 0; it < NIT; ++it){
    if (it + 3 < NIT){
      #pragma unroll
      for (int r = 0; r < 4; r++)
        qn[r] = CG ? __ldcg(xq[r] + (it+3)*8 + kl) : __ldg(xq[r] + (it+3)*8 + kl);
    }
    const int kb = (it*8 + kl)*4;
    #pragma unroll
    for (int c = 0; c < 6; ++c){
      float4 w = *(const float4*)&Wc[c*WS + kb];
      #pragma unroll
      for (int r = 0; r < 4; ++r){
        acc[r][c] = fmaf(q0[r].x, w.x, acc[r][c]);
        acc[r][c] = fmaf(q0[r].y, w.y, acc[r][c]);
        acc[r][c] = fmaf(q0[r].z, w.z, acc[r][c]);
        acc[r][c] = fmaf(q0[r].w, w.w, acc[r][c]);
      }
    }
    #pragma unroll
    for (int r = 0; r < 4; ++r){ q0[r] = q1[r]; q1[r] = q2[r]; q2[r] = qn[r]; }
  }
}

// 3-level butterfly over kl (within each 8-lane group); 24 accs.
// Lane kl keeps vals[q] for a = kl + 8q: r = a/6, cl = a%6.
__device__ __forceinline__ void reduce24(float (&acc)[4][6], float (&vals)[3], int kl){
  #pragma unroll
  for (int r = 0; r < 4; ++r){
    #pragma unroll
    for (int c = 0; c < 6; ++c){
      float v = acc[r][c];
      v += __shfl_xor_sync(0xffffffffu, v, 4);
      v += __shfl_xor_sync(0xffffffffu, v, 2);
      v += __shfl_xor_sync(0xffffffffu, v, 1);
      const int a = r*6 + c;
      if (kl == (a & 7)) vals[a >> 3] = v;
    }
  }
}

__global__ void __launch_bounds__(NT, 1)
act_kernel(const float* __restrict__ input, const float* __restrict__ Wih,
           const float* __restrict__ Whh, const float* __restrict__ bih,
           const float* __restrict__ bhh, const float* __restrict__ wpv,
           const float* __restrict__ bpv, float* __restrict__ out)
{
  extern __shared__ unsigned char smraw[];
  SM& s = *reinterpret_cast<SM*>(smraw);
  const int tid = threadIdx.x, blk = blockIdx.x;
  const int rg = blk >> 5, cg = blk & 31;
  const int row0 = rg*32, col0 = cg*24;
  const int lane = tid & 31, warp = tid >> 5;
  const int kl = lane & 7, cgp = lane >> 3;
  const int r0w = warp*4;
  const int c0t = cgp*6;              // thread's first column (of 24)

  // ---- one-time: stage weights ----
  for (int idx = tid; idx < 24*HH; idx += NT){
    int c = idx / HH, k = idx - c*HH;
    s.whh[c][k] = Whh[(size_t)(col0+c)*HH + k];
  }
  for (int idx = tid; idx < 24*DD; idx += NT){
    int c = idx / DD, k = idx - c*DD;
    s.wih[c][k] = Wih[(size_t)(col0+c)*(DD+1) + k];
  }
  if (tid < 24){
    s.flagw[tid] = Wih[(size_t)(col0+tid)*(DD+1) + DD];
    s.wp[tid]    = wpv[col0+tid];
    s.bias[tid]  = bih[col0+tid] + bhh[col0+tid];
  }
  if (tid < 32) s.pc[tid] = 0.f;
  for (int e = tid; e < 32*24; e += NT){
    int r2 = e/24, c2 = e - r2*24;
    g_hxi[0][row0+r2][col0+c2] = 0.f;
  }
  const float bp0 = bpv[0];
  int rb = 0;
  unsigned ep = g_flags[blk];   // epoch persists across graph replays

  for (int t = 0; t < TT; ++t){
    if (tid < 32){ s.ah[tid]=0.f; s.sc[tid]=0.f; s.spc[tid]=0.f; s.mask[tid]=1; }
    for (int e = tid; e < 32*24; e += NT){ int r2=e/24, c2=e-r2*24; s.ahx[r2][c2]=0.f; }
    __syncthreads();

    // ---- base = x_t @ W_ih^T + biases (reads input only) ----
    {
      float acc[4][6];
      #pragma unroll
      for (int r = 0; r < 4; r++)
        #pragma unroll
        for (int c = 0; c < 6; c++) acc[r][c] = 0.f;
      gemm6<8, 260, false>(acc, input + ((size_t)t*128 + row0 + r0w)*DD, DD,
                           &s.wih[c0t][0], kl);
      float vals[3];
      reduce24(acc, vals, kl);
      #pragma unroll
      for (int q = 0; q < 3; ++q){
        const int a = kl + 8*q;
        const int r = a / 6, cl = a - r*6;
        const int c = c0t + cl;
        s.base[r0w + r][c] = vals[q] + s.bias[c];
      }
    }

    // group barrier: protects previous step's carry (t=0: the zero-init)
    gbar(++ep, rg);

    // ---- ponder loop (group-local halting) ----
    for (int n = 0; n < 8; ++n){
      float acc[4][6];
      #pragma unroll
      for (int r = 0; r < 4; r++)
        #pragma unroll
        for (int c = 0; c < 6; c++) acc[r][c] = 0.f;
      gemm6<24, HH, true>(acc, &g_hxi[rb][row0 + r0w][0], HH,
                          &s.whh[c0t][0], kl);
      float vals[3];
      reduce24(acc, vals, kl);

      const float fl = (n == 0) ? 0.f : 1.f;
      // epilogue + warp-local pd (covers this warp's 4 rows)
      float p4[4] = {0.f, 0.f, 0.f, 0.f};
      #pragma unroll
      for (int q = 0; q < 3; ++q){
        const int a = kl + 8*q;
        const int r = a / 6, cl = a - r*6;
        const int c = c0t + cl;
        const int rr = r0w + r;
        float h = tanhf(vals[q] + s.base[rr][c] + fl*s.flagw[c]);
        s.hxn[rr][c] = h;
        p4[r] = fmaf(h, s.wp[c], p4[r]);
        int gr = row0 + rr, gc = col0 + c;
        float o = s.mask[rr] ? h : __ldcg(&g_hxi[rb][gr][gc]);
        g_hxi[rb^1][gr][gc] = o;
      }
      // full-warp butterfly: all lanes end with the 4 row sums
      #pragma unroll
      for (int r = 0; r < 4; ++r){
        float v = p4[r];
        v += __shfl_xor_sync(0xffffffffu, v, 16);
        v += __shfl_xor_sync(0xffffffffu, v, 8);
        v += __shfl_xor_sync(0xffffffffu, v, 4);
        v += __shfl_xor_sync(0xffffffffu, v, 2);
        v += __shfl_xor_sync(0xffffffffu, v, 1);
        p4[r] = v;
      }
      if (lane < 4)
        g_pd[(size_t)(n*128 + row0 + r0w + lane)*32 + cg] = p4[lane];
      gbar(++ep, rg);

      // redundant identical scalar update within group (fixed order)
      int nm = 0;
      if (tid < 32){
        const float4* pr4 = (const float4*)&g_pd[(size_t)(n*128 + row0 + tid)*32];
        float sum = 0.f;
        #pragma unroll
        for (int q = 0; q < 8; q++){
          float4 v4 = __ldcg(pr4 + q);
          sum += v4.x; sum += v4.y; sum += v4.z; sum += v4.w;
        }
        float h = 1.f/(1.f + expf(-(sum + bp0)));
        int   m  = s.mask[tid];
        float mf = m ? 1.f : 0.f;
        if (m) s.spc[tid] = -s.ah[tid];
        float ah2 = s.ah[tid] + mf*h;
        float p2  = h - fmaxf(ah2 - 1.f, 0.f);
        s.coef[tid] = mf*(1.f + p2);
        s.sc[tid]  += mf;
        s.ah[tid]   = ah2;
        int m2 = (ah2 < 0.99f);
        s.mask[tid] = m2;
        nm = m2;
      }
      int nlive = __syncthreads_or(nm);
      for (int e = tid; e < 32*24; e += NT){
        int r2 = e/24, c2 = e - r2*24;
        s.ahx[r2][c2] = fmaf(s.coef[r2], s.hxn[r2][c2], s.ahx[r2][c2]);
      }
      __syncthreads();
      rb ^= 1;
      if (!nlive) break;
    }

    // ---- end of step: outputs + carry (next step's post-base gbar protects) ----
    for (int e = tid; e < 32*24; e += NT){
      int r2 = e/24, c2 = e - r2*24;
      int gr2 = row0 + r2, gc2 = col0 + c2;
      float v = s.ahx[r2][c2] / s.sc[r2];
      out[(size_t)(t*128 + gr2)*HH + gc2] = v;
      if (t == TT-1) out[OFF_HXLAST + (size_t)gr2*HH + gc2] = v;
      g_hxi[rb][gr2][gc2] = v;
    }
    if (cg == 0 && tid < 32){
      s.pc[tid] += s.spc[tid];
      out[OFF_STEPS + t*128 + row0 + tid] = s.sc[tid];
    }
  }

  if (cg == 0 && tid < 32) out[OFF_PC + row0 + tid] = s.pc[tid];
}

extern "C" void kernel_launch(void* const* d_in, const int* in_sizes, int n_in,
                              void* d_out, int out_size)
{
  const float* input = (const float*)d_in[0];
  const float* Wih   = (const float*)d_in[1];
  const float* Whh   = (const float*)d_in[2];
  const float* bih   = (const float*)d_in[3];
  const float* bhh   = (const float*)d_in[4];
  const float* wpv   = (const float*)d_in[5];
  const float* bpv   = (const float*)d_in[6];
  (void)in_sizes; (void)n_in; (void)out_size;

  cudaFuncSetAttribute(act_kernel, cudaFuncAttributeMaxDynamicSharedMemorySize, (int)sizeof(SM));
  act_kernel<<<GRIDN, NT, sizeof(SM)>>>(input, Wih, Whh, bih, bhh, wpv, bpv, (float*)d_out);
}

// round 16
// speedup vs baseline: 1.1422x; 1.1422x over previous
#include <cuda_runtime.h>
#include <math.h>

#define TT 32
#define DD 256
#define HH 768
#define GRIDN 128
#define NT 256

#define OFF_HXLAST (TT*128*HH)
#define OFF_PC     (OFF_HXLAST + 128*HH)
#define OFF_STEPS  (OFF_PC + 128)

// persistent scratch (allocation-free rule)
__device__ float g_hxi[2][128][HH];               // double-buffered hidden state
__device__ float g_pd[8*128*32];                  // partial ponder dots [n][row][cg]
__device__ __align__(16) unsigned g_flags[GRIDN]; // barrier flags (monotonic)

struct SM {
  float whh[24][HH];     // W_hh rows for this block's 24 cols (73728 B)
  float wih[24][260];    // W_ih rows, k<256 (+pad)           (24960 B)
  float flagw[24];
  float wp[24];
  float bias[24];
  float ah[32], sc[32], spc[32], coef[32], pc[32];
  int   mask[32];
};

// group-scoped flag barrier: 32 blocks of this row group only
__device__ __forceinline__ void gbar(unsigned ep, int rg){
  __syncthreads();
  if (threadIdx.x == 0)
    asm volatile("st.release.gpu.global.u32 [%0], %1;"
                 :: "l"(&g_flags[blockIdx.x]), "r"(ep) : "memory");
  if (threadIdx.x < 8){
    const unsigned* fp = g_flags + rg*32 + threadIdx.x*4;
    for(;;){
      unsigned a,b,c,d;
      asm volatile("ld.relaxed.gpu.global.v4.u32 {%0,%1,%2,%3}, [%4];"
                   : "=r"(a),"=r"(b),"=r"(c),"=r"(d) : "l"(fp) : "memory");
      if ((int)(a-ep)>=0 && (int)(b-ep)>=0 && (int)(c-ep)>=0 && (int)(d-ep)>=0) break;
      __nanosleep(64);
    }
    asm volatile("fence.acq_rel.gpu;" ::: "memory");
  }
  __syncthreads();
}

// GEMM: warp = 4 rows x 24 cols as 2 column-halves (ch) x K-split 16 (kl).
// lane = ch*16 + kl. Per thread: acc[4][12], 2304 FFMA, 144 LDS.128, 48 LDG.128.
// W rows: [c][k], row stride WS floats. Depth-1 prefetch. (R12-proven kinematics)
template<int NIT, int WS, bool CG>
__device__ __forceinline__ void gemm16(float (&acc)[4][12],
    const float* xrow0, int xstride, const float* Wc, int kl)
{
  const float4* xq[4];
  #pragma unroll
  for (int r = 0; r < 4; r++) xq[r] = (const float4*)(xrow0 + r*xstride);

  float4 xv[4], xn[4];
  #pragma unroll
  for (int r = 0; r < 4; r++)
    xv[r] = CG ? __ldcg(xq[r] + kl) : __ldg(xq[r] + kl);

  #pragma unroll
  for (int it = 0; it < NIT; ++it){
    if (it + 1 < NIT){
      #pragma unroll
      for (int r = 0; r < 4; r++)
        xn[r] = CG ? __ldcg(xq[r] + (it+1)*16 + kl) : __ldg(xq[r] + (it+1)*16 + kl);
    }
    const int kb = (it*16 + kl)*4;
    #pragma unroll
    for (int c = 0; c < 12; ++c){
      float4 w = *(const float4*)&Wc[c*WS + kb];
      #pragma unroll
      for (int r = 0; r < 4; ++r){
        acc[r][c] = fmaf(xv[r].x, w.x, acc[r][c]);
        acc[r][c] = fmaf(xv[r].y, w.y, acc[r][c]);
        acc[r][c] = fmaf(xv[r].z, w.z, acc[r][c]);
        acc[r][c] = fmaf(xv[r].w, w.w, acc[r][c]);
      }
    }
    #pragma unroll
    for (int r = 0; r < 4; ++r) xv[r] = xn[r];
  }
}

// 4-level butterfly over kl within each 16-lane half; 48 accs.
// Lane kl keeps vals[q] for i = kl + 16q: r = i/12, cl = i%12.
__device__ __forceinline__ void reduce48(float (&acc)[4][12], float (&vals)[3], int kl){
  #pragma unroll
  for (int r = 0; r < 4; ++r){
    #pragma unroll
    for (int c = 0; c < 12; ++c){
      float v = acc[r][c];
      v += __shfl_xor_sync(0xffffffffu, v, 8);
      v += __shfl_xor_sync(0xffffffffu, v, 4);
      v += __shfl_xor_sync(0xffffffffu, v, 2);
      v += __shfl_xor_sync(0xffffffffu, v, 1);
      const int i = r*12 + c;
      if (kl == (i & 15)) vals[i >> 4] = v;
    }
  }
}

__global__ void __launch_bounds__(NT, 1)
act_kernel(const float* __restrict__ input, const float* __restrict__ Wih,
           const float* __restrict__ Whh, const float* __restrict__ bih,
           const float* __restrict__ bhh, const float* __restrict__ wpv,
           const float* __restrict__ bpv, float* __restrict__ out)
{
  extern __shared__ unsigned char smraw[];
  SM& s = *reinterpret_cast<SM*>(smraw);
  const int tid = threadIdx.x, blk = blockIdx.x;
  const int rg = blk >> 5, cg = blk & 31;
  const int row0 = rg*32, col0 = cg*24;
  const int lane = tid & 31, warp = tid >> 5;
  const int kl = lane & 15, ch = lane >> 4;
  const int r0w = warp*4;

  // per-thread epilogue coordinates for q = 0,1,2 (i = kl + 16q)
  int rr_q[3], c_q[3];
  #pragma unroll
  for (int q = 0; q < 3; ++q){
    const int i = kl + 16*q;
    rr_q[q] = r0w + i/12;
    c_q[q]  = ch*12 + (i % 12);
  }

  // ---- one-time: stage weights ----
  for (int idx = tid; idx < 24*HH; idx += NT){
    int c = idx / HH, k = idx - c*HH;
    s.whh[c][k] = Whh[(size_t)(col0+c)*HH + k];
  }
  for (int idx = tid; idx < 24*DD; idx += NT){
    int c = idx / DD, k = idx - c*DD;
    s.wih[c][k] = Wih[(size_t)(col0+c)*(DD+1) + k];
  }
  if (tid < 24){
    s.flagw[tid] = Wih[(size_t)(col0+tid)*(DD+1) + DD];
    s.wp[tid]    = wpv[col0+tid];
    s.bias[tid]  = bih[col0+tid] + bhh[col0+tid];
  }
  if (tid < 32) s.pc[tid] = 0.f;
  for (int e = tid; e < 32*24; e += NT){
    int r2 = e/24, c2 = e - r2*24;
    g_hxi[0][row0+r2][col0+c2] = 0.f;
  }
  const float bp0 = bpv[0];
  int rb = 0;
  unsigned ep = g_flags[blk];   // epoch persists across graph replays

  for (int t = 0; t < TT; ++t){
    __syncthreads();   // previous step's output reads (s.sc) done before reset
    if (tid < 32){ s.ah[tid]=0.f; s.sc[tid]=0.f; s.spc[tid]=0.f; s.mask[tid]=1; }

    float ahx_q[3] = {0.f, 0.f, 0.f};
    float base_q[3];

    // ---- base = x_t @ W_ih^T + biases (register-resident; reads input only) ----
    {
      float acc[4][12];
      #pragma unroll
      for (int r = 0; r < 4; r++)
        #pragma unroll
        for (int c = 0; c < 12; c++) acc[r][c] = 0.f;
      gemm16<4, 260, false>(acc, input + ((size_t)t*128 + row0 + r0w)*DD, DD,
                            &s.wih[ch*12][0], kl);
      float vals[3];
      reduce48(acc, vals, kl);
      #pragma unroll
      for (int q = 0; q < 3; ++q)
        base_q[q] = vals[q] + s.bias[c_q[q]];
    }

    // group barrier: protects previous step's carry (t=0: the zero-init)
    gbar(++ep, rg);

    // ---- ponder loop (group-local halting) ----
    for (int n = 0; n < 8; ++n){
      float acc[4][12];
      #pragma unroll
      for (int r = 0; r < 4; r++)
        #pragma unroll
        for (int c = 0; c < 12; c++) acc[r][c] = 0.f;
      gemm16<12, HH, true>(acc, &g_hxi[rb][row0 + r0w][0], HH,
                           &s.whh[ch*12][0], kl);
      float vals[3];
      reduce48(acc, vals, kl);

      const float fl = (n == 0) ? 0.f : 1.f;
      float h_q[3];
      float p4[4] = {0.f, 0.f, 0.f, 0.f};
      #pragma unroll
      for (int q = 0; q < 3; ++q){
        const int rr = rr_q[q], c = c_q[q];
        float h = tanhf(vals[q] + base_q[q] + fl*s.flagw[c]);
        h_q[q] = h;
        p4[rr - r0w] = fmaf(h, s.wp[c], p4[rr - r0w]);
        int gr = row0 + rr, gc = col0 + c;
        float o = s.mask[rr] ? h : __ldcg(&g_hxi[rb][gr][gc]);
        g_hxi[rb^1][gr][gc] = o;
      }
      // warp-local pd: butterfly the 4 row-dots (warp covers 4 rows x 24 cols)
      #pragma unroll
      for (int r = 0; r < 4; ++r){
        float v = p4[r];
        v += __shfl_xor_sync(0xffffffffu, v, 16);
        v += __shfl_xor_sync(0xffffffffu, v, 8);
        v += __shfl_xor_sync(0xffffffffu, v, 4);
        v += __shfl_xor_sync(0xffffffffu, v, 2);
        v += __shfl_xor_sync(0xffffffffu, v, 1);
        p4[r] = v;
      }
      if (lane < 4)
        g_pd[(size_t)(n*128 + row0 + r0w + lane)*32 + cg] = p4[lane];
      gbar(++ep, rg);

      // redundant identical scalar update within group (fixed order)
      int nm = 0;
      if (tid < 32){
        const float4* pr4 = (const float4*)&g_pd[(size_t)(n*128 + row0 + tid)*32];
        float sum = 0.f;
        #pragma unroll
        for (int q = 0; q < 8; q++){
          float4 v4 = __ldcg(pr4 + q);
          sum += v4.x; sum += v4.y; sum += v4.z; sum += v4.w;
        }
        float h = 1.f/(1.f + expf(-(sum + bp0)));
        int   m  = s.mask[tid];
        float mf = m ? 1.f : 0.f;
        if (m) s.spc[tid] = -s.ah[tid];
        float ah2 = s.ah[tid] + mf*h;
        float p2  = h - fmaxf(ah2 - 1.f, 0.f);
        s.coef[tid] = mf*(1.f + p2);
        s.sc[tid]  += mf;
        s.ah[tid]   = ah2;
        int m2 = (ah2 < 0.99f);
        s.mask[tid] = m2;
        nm = m2;
      }
      int nlive = __syncthreads_or(nm);
      #pragma unroll
      for (int q = 0; q < 3; ++q)
        ahx_q[q] = fmaf(s.coef[rr_q[q]], h_q[q], ahx_q[q]);
      rb ^= 1;
      if (!nlive) break;
    }

    // ---- end of step: outputs + carry (next step's post-base gbar protects) ----
    #pragma unroll
    for (int q = 0; q < 3; ++q){
      const int rr = rr_q[q], c = c_q[q];
      const int gr = row0 + rr, gc = col0 + c;
      float v = ahx_q[q] / s.sc[rr];
      out[(size_t)(t*128 + gr)*HH + gc] = v;
      if (t == TT-1) out[OFF_HXLAST + (size_t)gr*HH + gc] = v;
      g_hxi[rb][gr][gc] = v;
    }
    if (cg == 0 && tid < 32){
      s.pc[tid] += s.spc[tid];
      out[OFF_STEPS + t*128 + row0 + tid] = s.sc[tid];
    }
  }

  if (cg == 0 && tid < 32) out[OFF_PC + row0 + tid] = s.pc[tid];
}

extern "C" void kernel_launch(void* const* d_in, const int* in_sizes, int n_in,
                              void* d_out, int out_size)
{
  const float* input = (const float*)d_in[0];
  const float* Wih   = (const float*)d_in[1];
  const float* Whh   = (const float*)d_in[2];
  const float* bih   = (const float*)d_in[3];
  const float* bhh   = (const float*)d_in[4];
  const float* wpv   = (const float*)d_in[5];
  const float* bpv   = (const float*)d_in[6];
  (void)in_sizes; (void)n_in; (void)out_size;

  cudaFuncSetAttribute(act_kernel, cudaFuncAttributeMaxDynamicSharedMemorySize, (int)sizeof(SM));
  act_kernel<<<GRIDN, NT, sizeof(SM)>>>(input, Wih, Whh, bih, bhh, wpv, bpv, (float*)d_out);
}